// round 12
// baseline (speedup 1.0000x reference)
#include <cuda_runtime.h>
#include <cuda_fp16.h>
#include <cstdint>
#include <math.h>

#define BATCH 4
#define SEQ 2048
#define DMODEL 1024
#define NH 16
#define DHEAD 64
#define MTOT (BATCH*SEQ)                 /* 8192 rows */
#define PSZ (BATCH*NH*SEQ*DHEAD)         /* 8,388,608 */
#define BQ 128
#define BK 64
#define QSCALE 0.18033688011112042f     /* log2(e)/8 */

// ---------------- device scratch ----------------
__device__ __align__(128) __half  g_q[PSZ];                  // fp16, pre-scaled by log2e/8
__device__ __align__(128) __half  g_k[PSZ];
__device__ __align__(128) __half  g_v[PSZ];
__device__ __align__(128) __half  g_x[MTOT*DMODEL];
__device__ __align__(128) __half  g_z[MTOT*DMODEL];
__device__ __align__(128) __half  g_wqkv[3*DMODEL*DMODEL];   // [n=(proj,h,e)][k]
__device__ __align__(128) __half  g_wo[DMODEL*DMODEL];       // [n][k] = Wo^T
__device__ __align__(128) float   g_bqkv[3*DMODEL];

// ---------------- helpers ----------------
__device__ __forceinline__ uint32_t smem_u32(const void* p) {
    uint32_t a;
    asm("{ .reg .u64 t; cvta.to.shared.u64 t, %1; cvt.u32.u64 %0, t; }"
        : "=r"(a) : "l"(p));
    return a;
}
__device__ __forceinline__ uint32_t cvt2h(float lo, float hi) {
    uint32_t r;
    asm("cvt.rn.f16x2.f32 %0, %1, %2;" : "=r"(r) : "f"(hi), "f"(lo));
    return r;
}
__device__ __forceinline__ void cpasync16(uint32_t saddr, const void* g) {
    asm volatile("cp.async.cg.shared.global [%0], [%1], 16;"
                 :: "r"(saddr), "l"(g) : "memory");
}
__device__ __forceinline__ void ldsm4(uint32_t& r0, uint32_t& r1,
                                      uint32_t& r2, uint32_t& r3, uint32_t addr) {
    asm volatile("ldmatrix.sync.aligned.m8n8.x4.shared.b16 {%0,%1,%2,%3}, [%4];"
                 : "=r"(r0), "=r"(r1), "=r"(r2), "=r"(r3) : "r"(addr));
}
__device__ __forceinline__ void ldsm4t(uint32_t& r0, uint32_t& r1,
                                       uint32_t& r2, uint32_t& r3, uint32_t addr) {
    asm volatile("ldmatrix.sync.aligned.m8n8.x4.trans.shared.b16 {%0,%1,%2,%3}, [%4];"
                 : "=r"(r0), "=r"(r1), "=r"(r2), "=r"(r3) : "r"(addr));
}
__device__ __forceinline__ void mma16816(float* d, const uint32_t* a, const uint32_t* b) {
    asm volatile("mma.sync.aligned.m16n8k16.row.col.f32.f16.f16.f32 "
                 "{%0,%1,%2,%3},{%4,%5,%6,%7},{%8,%9},{%0,%1,%2,%3};"
                 : "+f"(d[0]), "+f"(d[1]), "+f"(d[2]), "+f"(d[3])
                 : "r"(a[0]), "r"(a[1]), "r"(a[2]), "r"(a[3]),
                   "r"(b[0]), "r"(b[1]));
}
// swizzle for [rows x 128B] tiles (8 x 16B units)
__device__ __forceinline__ uint32_t swz128(int r, int u) {
    return (uint32_t)(r * 128 + ((u ^ (r & 7)) << 4));
}

// ---------------------------------------------------------------------------
// Preprocess kernels
// ---------------------------------------------------------------------------
__global__ void convert_x_kernel(const float* __restrict__ x) {
    size_t i = ((size_t)blockIdx.x * 256 + threadIdx.x) * 4;
    float4 v = *(const float4*)(x + i);
    *(uint2*)&g_x[i] = make_uint2(cvt2h(v.x, v.y), cvt2h(v.z, v.w));
}

__global__ void repack_wqkv_kernel(const float* __restrict__ Wq,
                                   const float* __restrict__ Wk,
                                   const float* __restrict__ Wv,
                                   const float* __restrict__ bq,
                                   const float* __restrict__ bk,
                                   const float* __restrict__ bv) {
    __shared__ float t[64][65];
    const int tid = threadIdx.x;
    const int k0 = blockIdx.x * 64;
    const int cy = blockIdx.y;            // 0..47
    const int proj = cy >> 4, h = cy & 15;
    const float* W = (proj == 0) ? Wq : (proj == 1 ? Wk : Wv);
    const float* base = W + (size_t)h * DMODEL * DHEAD;
    if (k0 == 0 && tid < 64) {
        const float* bb = (proj == 0) ? bq : (proj == 1 ? bk : bv);
        g_bqkv[proj*1024 + h*64 + tid] = bb[h*64 + tid];
    }
    #pragma unroll
    for (int it = 0; it < 4; ++it) {
        int idx = it*256 + tid;
        int r = idx >> 4;
        int c4 = (idx & 15) << 2;
        float4 v = *(const float4*)(base + (size_t)(k0 + r)*DHEAD + c4);
        t[r][c4+0] = v.x; t[r][c4+1] = v.y; t[r][c4+2] = v.z; t[r][c4+3] = v.w;
    }
    __syncthreads();
    const int n0 = proj*1024 + h*64;
    #pragma unroll
    for (int it = 0; it < 4; ++it) {
        int idx = it*256 + tid;
        int e = idx >> 4;
        int kk = (idx & 15) << 2;
        size_t off = (size_t)(n0 + e)*DMODEL + k0 + kk;
        *(uint2*)&g_wqkv[off] = make_uint2(cvt2h(t[kk+0][e], t[kk+1][e]),
                                           cvt2h(t[kk+2][e], t[kk+3][e]));
    }
}

__global__ void repack_wo_kernel(const float* __restrict__ Wo) {
    __shared__ float t[64][65];
    const int tid = threadIdx.x;
    const int k0 = blockIdx.x * 64;
    const int n0 = blockIdx.y * 64;
    #pragma unroll
    for (int it = 0; it < 4; ++it) {
        int idx = it*256 + tid;
        int r = idx >> 4;
        int c4 = (idx & 15) << 2;
        float4 v = *(const float4*)(Wo + (size_t)(k0 + r)*DMODEL + n0 + c4);
        t[r][c4+0] = v.x; t[r][c4+1] = v.y; t[r][c4+2] = v.z; t[r][c4+3] = v.w;
    }
    __syncthreads();
    #pragma unroll
    for (int it = 0; it < 4; ++it) {
        int idx = it*256 + tid;
        int e = idx >> 4;
        int kk = (idx & 15) << 2;
        size_t off = (size_t)(n0 + e)*DMODEL + k0 + kk;
        *(uint2*)&g_wo[off] = make_uint2(cvt2h(t[kk+0][e], t[kk+1][e]),
                                         cvt2h(t[kk+2][e], t[kk+3][e]));
    }
}

// ---------------------------------------------------------------------------
// mma.sync fp16 GEMM. 256 threads, 8 warps (2m x 4n), warp tile 64x32.
// K-chunk 64, 4-stage cp.async ring, register double-buffered fragments:
// frags[ks+1] LDSMs issue between the MMAs of ks -> LDS latency hidden.
// MODE 0: A=g_x, B=g_wqkv, bias=g_bqkv -> g_q (scaled log2e/8), g_k, g_v
// MODE 1: A=g_z, B=g_wo, bias=bo -> Cout fp32
// ---------------------------------------------------------------------------
#define BKC 64
#define GSTAGE 32768u
#define GSTAGES 4
#define GEMM_SMEM (GSTAGES*32768)
#define GKT (DMODEL/BKC)   /* 16 chunks */

template<int MODE>
__global__ __launch_bounds__(256)
void mma_gemm_kernel(const float* __restrict__ bias_ext, float* __restrict__ Cout) {
    extern __shared__ char smem[];
    const uint32_t sbase = smem_u32(smem);
    const int tid  = threadIdx.x;
    const int lane = tid & 31;
    const int wid  = tid >> 5;
    const int wm   = wid & 1;
    const int wn   = wid >> 1;
    const int m0 = blockIdx.y * 128;
    const int n0 = blockIdx.x * 128;

    const __half* A = (MODE == 0) ? g_x : g_z;
    const __half* B = (MODE == 0) ? g_wqkv : g_wo;

    // loader: 2 base pointers; per c (0..3) step is +32 rows = +32*DMODEL elems,
    // smem step +4096B (swizzle invariant to +32 rows since r&7 unchanged).
    const int ldr = tid >> 3, ldu = tid & 7;
    const __half* baseA = A + (size_t)(m0 + ldr)*DMODEL + ldu*8;
    const __half* baseB = B + (size_t)(n0 + ldr)*DMODEL + ldu*8;
    const uint32_t so0 = swz128(ldr, ldu);

    const int a_r  = lane & 15;
    const int luh  = lane >> 4;
    const int b_r  = (lane & 7) + ((lane >> 3) & 1) * 8;

    float acc[4][4][4] = {};

    // prologue: stages 0..GSTAGES-2
    #pragma unroll
    for (int s = 0; s < GSTAGES-1; ++s) {
        uint32_t st = sbase + s*GSTAGE;
        #pragma unroll
        for (int c = 0; c < 4; ++c) {
            cpasync16(st + so0 + c*4096u,           baseA + s*BKC + (size_t)c*32*DMODEL);
            cpasync16(st + 16384u + so0 + c*4096u,  baseB + s*BKC + (size_t)c*32*DMODEL);
        }
        asm volatile("cp.async.commit_group;" ::: "memory");
    }

    uint32_t ah[2][4][4], bh[2][4][2];

    #pragma unroll 1
    for (int kt = 0; kt < GKT; ++kt) {
        if (kt < GKT - 1) asm volatile("cp.async.wait_group %0;" :: "n"(GSTAGES-2) : "memory");
        else              asm volatile("cp.async.wait_group 0;" ::: "memory");
        __syncthreads();
        if (kt + GSTAGES - 1 < GKT) {
            uint32_t st = sbase + (uint32_t)((kt + GSTAGES - 1) % GSTAGES) * GSTAGE;
            #pragma unroll
            for (int c = 0; c < 4; ++c) {
                cpasync16(st + so0 + c*4096u,
                          baseA + (kt + GSTAGES - 1)*BKC + (size_t)c*32*DMODEL);
                cpasync16(st + 16384u + so0 + c*4096u,
                          baseB + (kt + GSTAGES - 1)*BKC + (size_t)c*32*DMODEL);
            }
            asm volatile("cp.async.commit_group;" ::: "memory");
        }

        const uint32_t st = sbase + (uint32_t)(kt % GSTAGES) * GSTAGE;

        // load ks=0 fragments into buffer 0
        {
            const int u = luh;
            #pragma unroll
            for (int mi = 0; mi < 4; ++mi)
                ldsm4(ah[0][mi][0], ah[0][mi][1], ah[0][mi][2], ah[0][mi][3],
                      st + swz128(wm*64 + mi*16 + a_r, u));
            #pragma unroll
            for (int g = 0; g < 2; ++g) {
                uint32_t t0, t1, t2, t3;
                ldsm4(t0, t1, t2, t3, st + 16384u + swz128(wn*32 + g*16 + b_r, u));
                bh[0][g*2][0] = t0; bh[0][g*2][1] = t2;
                bh[0][g*2+1][0] = t1; bh[0][g*2+1][1] = t3;
            }
        }
        #pragma unroll
        for (int ks = 0; ks < 4; ++ks) {
            const int cur = ks & 1, nxt = cur ^ 1;
            if (ks < 3) {
                const int u = (ks+1)*2 + luh;
                #pragma unroll
                for (int mi = 0; mi < 4; ++mi)
                    ldsm4(ah[nxt][mi][0], ah[nxt][mi][1], ah[nxt][mi][2], ah[nxt][mi][3],
                          st + swz128(wm*64 + mi*16 + a_r, u));
                #pragma unroll
                for (int g = 0; g < 2; ++g) {
                    uint32_t t0, t1, t2, t3;
                    ldsm4(t0, t1, t2, t3, st + 16384u + swz128(wn*32 + g*16 + b_r, u));
                    bh[nxt][g*2][0] = t0; bh[nxt][g*2][1] = t2;
                    bh[nxt][g*2+1][0] = t1; bh[nxt][g*2+1][1] = t3;
                }
            }
            #pragma unroll
            for (int mi = 0; mi < 4; ++mi)
                #pragma unroll
                for (int nb = 0; nb < 4; ++nb)
                    mma16816(acc[mi][nb], ah[cur][mi], bh[cur][nb]);
        }
    }

    // epilogue
    const float* bias = (MODE == 0) ? g_bqkv : bias_ext;
    #pragma unroll
    for (int nb = 0; nb < 4; ++nb) {
        const int ncol = n0 + wn*32 + nb*8 + (lane & 3)*2;
        const float b0 = bias[ncol], b1 = bias[ncol + 1];
        #pragma unroll
        for (int mi = 0; mi < 4; ++mi) {
            const int m = m0 + wm*64 + mi*16 + (lane >> 2);
            float v00 = acc[mi][nb][0] + b0, v01 = acc[mi][nb][1] + b1; // row m
            float v10 = acc[mi][nb][2] + b0, v11 = acc[mi][nb][3] + b1; // row m+8
            if (MODE == 0) {
                const int proj = ncol >> 10, h = (ncol >> 6) & 15, e0 = ncol & 63;
                if (proj == 0) { v00 *= QSCALE; v01 *= QSCALE; v10 *= QSCALE; v11 *= QSCALE; }
                const int b = m >> 11, s = m & 2047;
                __half* dst = (proj == 0 ? g_q : (proj == 1 ? g_k : g_v))
                            + (((size_t)(b*NH + h))*SEQ + s)*DHEAD + e0;
                *(uint32_t*)dst = cvt2h(v00, v01);
                *(uint32_t*)(dst + 8*DHEAD) = cvt2h(v10, v11);
            } else {
                *(float2*)(Cout + (size_t)m*DMODEL + ncol)       = make_float2(v00, v01);
                *(float2*)(Cout + (size_t)(m + 8)*DMODEL + ncol) = make_float2(v10, v11);
            }
        }
    }
}

// ---------------------------------------------------------------------------
// Flash attention, fp16, fixed-max softmax (p = 2^s), 3-stage.
// 256 threads, 8 warps x 16 q-rows (R10 geometry). V-fragments register
// double-buffered in the PV phase.
// SMEM: [0,16K) Q [128][64]; slot s at 16384+s*16384: K(8K)|V(8K).
// ---------------------------------------------------------------------------
#define ATTN_SMEM (16384 + 3*16384)
#define AKT (SEQ/BK)   /* 32 tiles */

__global__ __launch_bounds__(256)
void attn_mma_kernel() {
    extern __shared__ char smem[];
    const uint32_t sb = smem_u32(smem);
    const int tid  = threadIdx.x;
    const int lane = tid & 31;
    const int w    = tid >> 5;
    const int bh   = blockIdx.y;
    const int s0   = blockIdx.x * BQ;

    const __half* q_g = g_q + ((size_t)bh*SEQ + s0)*DHEAD;
    const __half* k_g = g_k + (size_t)bh*SEQ*DHEAD;
    const __half* v_g = g_v + (size_t)bh*SEQ*DHEAD;

    const __half* t_src[4];
    uint32_t t_soff[4];
    #pragma unroll
    for (int c = 0; c < 4; ++c) {
        int linear = c*256 + tid;
        int tile = linear >> 9;            // 0:K 1:V
        int idx  = linear & 511;
        int r = idx >> 3, u = idx & 7;
        t_src[c] = (tile ? v_g : k_g) + (size_t)r*DHEAD + u*8;
        t_soff[c] = (uint32_t)tile*8192u + swz128(r, u);
    }

    #pragma unroll
    for (int c = 0; c < 4; ++c) {
        int idx = c*256 + tid;
        int r = idx >> 3, u = idx & 7;
        cpasync16(sb + swz128(r, u), q_g + (size_t)r*DHEAD + u*8);
    }
    #pragma unroll
    for (int c = 0; c < 4; ++c) cpasync16(sb + 16384u + t_soff[c], t_src[c]);
    asm volatile("cp.async.commit_group;" ::: "memory");
    #pragma unroll
    for (int c = 0; c < 4; ++c) cpasync16(sb + 32768u + t_soff[c], t_src[c] + (size_t)BK*DHEAD);
    asm volatile("cp.async.commit_group;" ::: "memory");

    const int a_r = lane & 15;
    const int lu  = lane >> 4;
    const int b_r = (lane & 7) + ((lane >> 3) & 1) * 8;

    asm volatile("cp.async.wait_group 1;" ::: "memory");
    __syncthreads();
    uint32_t qh[4][4];
    #pragma unroll
    for (int ks = 0; ks < 4; ++ks) {
        uint32_t so = swz128(w*16 + a_r, ks*2 + lu);
        ldsm4(qh[ks][0], qh[ks][1], qh[ks][2], qh[ks][3], sb + so);
    }

    float oacc[8][4] = {};
    float l0 = 0.f, l1 = 0.f;

    #pragma unroll 1
    for (int kt = 0; kt < AKT; ++kt) {
        if (kt < AKT - 1) asm volatile("cp.async.wait_group 1;" ::: "memory");
        else              asm volatile("cp.async.wait_group 0;" ::: "memory");
        __syncthreads();
        if (kt + 2 < AKT) {
            uint32_t st = sb + 16384u + (uint32_t)((kt + 2) % 3) * 16384u;
            #pragma unroll
            for (int c = 0; c < 4; ++c)
                cpasync16(st + t_soff[c], t_src[c] + (size_t)(kt + 2)*BK*DHEAD);
            asm volatile("cp.async.commit_group;" ::: "memory");
        }
        const uint32_t st = sb + 16384u + (uint32_t)(kt % 3) * 16384u;

        // ---- QK ----
        float sacc[8][4] = {};
        #pragma unroll
        for (int ks = 0; ks < 4; ++ks) {
            uint32_t kh2[8][2];
            #pragma unroll
            for (int g = 0; g < 4; ++g) {
                uint32_t so = swz128(g*16 + b_r, ks*2 + lu);
                uint32_t t0, t1, t2, t3;
                ldsm4(t0, t1, t2, t3, st + so);
                kh2[g*2][0] = t0; kh2[g*2][1] = t2;
                kh2[g*2+1][0] = t1; kh2[g*2+1][1] = t3;
            }
            #pragma unroll
            for (int nb = 0; nb < 8; ++nb)
                mma16816(sacc[nb], qh[ks], kh2[nb]);
        }

        // ---- p = 2^s ----
        uint32_t ph[4][4];
        #pragma unroll
        for (int nb = 0; nb < 8; ++nb) {
            float p0 = exp2f(sacc[nb][0]);
            float p1 = exp2f(sacc[nb][1]);
            float p2 = exp2f(sacc[nb][2]);
            float p3 = exp2f(sacc[nb][3]);
            l0 += p0 + p1; l1 += p2 + p3;
            const int ks = nb >> 1;
            const int rb = (nb & 1) * 2;
            ph[ks][rb+0] = cvt2h(p0, p1);
            ph[ks][rb+1] = cvt2h(p2, p3);
        }

        // ---- PV with V-fragment double buffering ----
        uint32_t vb[2][8][2];
        {
            #pragma unroll
            for (int np = 0; np < 4; ++np) {
                uint32_t so = swz128(0*16 + b_r, np*2 + lu);
                uint32_t t0, t1, t2, t3;
                ldsm4t(t0, t1, t2, t3, st + 8192u + so);
                vb[0][np*2][0] = t0; vb[0][np*2][1] = t1;
                vb[0][np*2+1][0] = t2; vb[0][np*2+1][1] = t3;
            }
        }
        #pragma unroll
        for (int ks = 0; ks < 4; ++ks) {
            const int cur = ks & 1, nxt = cur ^ 1;
            if (ks < 3) {
                #pragma unroll
                for (int np = 0; np < 4; ++np) {
                    uint32_t so = swz128((ks+1)*16 + b_r, np*2 + lu);
                    uint32_t t0, t1, t2, t3;
                    ldsm4t(t0, t1, t2, t3, st + 8192u + so);
                    vb[nxt][np*2][0] = t0; vb[nxt][np*2][1] = t1;
                    vb[nxt][np*2+1][0] = t2; vb[nxt][np*2+1][1] = t3;
                }
            }
            #pragma unroll
            for (int nb = 0; nb < 8; ++nb)
                mma16816(oacc[nb], ph[ks], vb[cur][nb]);
        }
    }

    l0 += __shfl_xor_sync(0xffffffffu, l0, 1);
    l0 += __shfl_xor_sync(0xffffffffu, l0, 2);
    l1 += __shfl_xor_sync(0xffffffffu, l1, 1);
    l1 += __shfl_xor_sync(0xffffffffu, l1, 2);

    const float inv0 = 1.0f / l0, inv1 = 1.0f / l1;
    const int b = bh >> 4, h = bh & 15;
    const int r0 = s0 + w*16 + (lane >> 2);
    #pragma unroll
    for (int nb = 0; nb < 8; ++nb) {
        const int c = h*64 + nb*8 + (lane & 3)*2;
        size_t o0 = ((size_t)b*SEQ + r0)*DMODEL + c;
        *(uint32_t*)&g_z[o0] =
            cvt2h(oacc[nb][0]*inv0, oacc[nb][1]*inv0);
        *(uint32_t*)&g_z[o0 + 8*DMODEL] =
            cvt2h(oacc[nb][2]*inv1, oacc[nb][3]*inv1);
    }
}

// ---------------------------------------------------------------------------
extern "C" void kernel_launch(void* const* d_in, const int* in_sizes, int n_in,
                              void* d_out, int out_size) {
    const float* x  = (const float*)d_in[0];
    const float* Wq = (const float*)d_in[1];
    const float* bq = (const float*)d_in[2];
    const float* Wk = (const float*)d_in[3];
    const float* bk = (const float*)d_in[4];
    const float* Wv = (const float*)d_in[5];
    const float* bv = (const float*)d_in[6];
    const float* Wo = (const float*)d_in[7];
    const float* bo = (const float*)d_in[8];
    float* out = (float*)d_out;

    cudaFuncSetAttribute(attn_mma_kernel,
                         cudaFuncAttributeMaxDynamicSharedMemorySize, ATTN_SMEM);
    cudaFuncSetAttribute(mma_gemm_kernel<0>,
                         cudaFuncAttributeMaxDynamicSharedMemorySize, GEMM_SMEM);
    cudaFuncSetAttribute(mma_gemm_kernel<1>,
                         cudaFuncAttributeMaxDynamicSharedMemorySize, GEMM_SMEM);

    // preprocessing
    convert_x_kernel<<<(MTOT*DMODEL)/1024, 256>>>(x);
    repack_wqkv_kernel<<<dim3(16, 48), 256>>>(Wq, Wk, Wv, bq, bk, bv);
    repack_wo_kernel<<<dim3(16, 16), 256>>>(Wo);

    // QKV projection (fp16) -> g_q (scaled log2e/8), g_k, g_v
    mma_gemm_kernel<0><<<dim3(24, 64), 256, GEMM_SMEM>>>(nullptr, nullptr);

    // flash attention (fp16 tensor core, fixed-max softmax) -> g_z
    attn_mma_kernel<<<dim3(SEQ/BQ, BATCH*NH), 256, ATTN_SMEM>>>();

    // output projection (fp16) -> out
    mma_gemm_kernel<1><<<dim3(8, 64), 256, GEMM_SMEM>>>(bo, out);
}

// round 13
// speedup vs baseline: 1.0863x; 1.0863x over previous
#include <cuda_runtime.h>
#include <cuda_fp16.h>
#include <cstdint>
#include <math.h>

#define BATCH 4
#define SEQ 2048
#define DMODEL 1024
#define NH 16
#define DHEAD 64
#define MTOT (BATCH*SEQ)                 /* 8192 rows */
#define PSZ (BATCH*NH*SEQ*DHEAD)         /* 8,388,608 */
#define BQ 128
#define BK 64
#define QSCALE 0.18033688011112042f     /* log2(e)/8 */

// ---------------- device scratch ----------------
__device__ __align__(128) __half  g_q[PSZ];                  // fp16, pre-scaled by log2e/8
__device__ __align__(128) __half  g_k[PSZ];
__device__ __align__(128) __half  g_v[PSZ];
__device__ __align__(128) __half  g_x[MTOT*DMODEL];
__device__ __align__(128) __half  g_z[MTOT*DMODEL];
__device__ __align__(128) __half  g_wqkv[3*DMODEL*DMODEL];   // [n=(proj,h,e)][k]
__device__ __align__(128) __half  g_wo[DMODEL*DMODEL];       // [n][k] = Wo^T
__device__ __align__(128) float   g_bqkv[3*DMODEL];

// ---------------- helpers ----------------
__device__ __forceinline__ uint32_t smem_u32(const void* p) {
    uint32_t a;
    asm("{ .reg .u64 t; cvta.to.shared.u64 t, %1; cvt.u32.u64 %0, t; }"
        : "=r"(a) : "l"(p));
    return a;
}
// pack two floats into fp16x2 (lo in low half, hi in high half)
__device__ __forceinline__ uint32_t cvt2h(float lo, float hi) {
    uint32_t r;
    asm("cvt.rn.f16x2.f32 %0, %1, %2;" : "=r"(r) : "f"(hi), "f"(lo));
    return r;
}
__device__ __forceinline__ uint32_t ex2h2(uint32_t s) {
    uint32_t r;
    asm("ex2.approx.f16x2 %0, %1;" : "=r"(r) : "r"(s));
    return r;
}
__device__ __forceinline__ void cpasync16(uint32_t saddr, const void* g) {
    asm volatile("cp.async.cg.shared.global [%0], [%1], 16;"
                 :: "r"(saddr), "l"(g) : "memory");
}
__device__ __forceinline__ void ldsm4(uint32_t& r0, uint32_t& r1,
                                      uint32_t& r2, uint32_t& r3, uint32_t addr) {
    asm volatile("ldmatrix.sync.aligned.m8n8.x4.shared.b16 {%0,%1,%2,%3}, [%4];"
                 : "=r"(r0), "=r"(r1), "=r"(r2), "=r"(r3) : "r"(addr));
}
__device__ __forceinline__ void ldsm4t(uint32_t& r0, uint32_t& r1,
                                       uint32_t& r2, uint32_t& r3, uint32_t addr) {
    asm volatile("ldmatrix.sync.aligned.m8n8.x4.trans.shared.b16 {%0,%1,%2,%3}, [%4];"
                 : "=r"(r0), "=r"(r1), "=r"(r2), "=r"(r3) : "r"(addr));
}
__device__ __forceinline__ void mma16816(float* d, const uint32_t* a, const uint32_t* b) {
    asm volatile("mma.sync.aligned.m16n8k16.row.col.f32.f16.f16.f32 "
                 "{%0,%1,%2,%3},{%4,%5,%6,%7},{%8,%9},{%0,%1,%2,%3};"
                 : "+f"(d[0]), "+f"(d[1]), "+f"(d[2]), "+f"(d[3])
                 : "r"(a[0]), "r"(a[1]), "r"(a[2]), "r"(a[3]),
                   "r"(b[0]), "r"(b[1]));
}
// swizzle for [rows x 128B] tiles (8 x 16B units)
__device__ __forceinline__ uint32_t swz128(int r, int u) {
    return (uint32_t)(r * 128 + ((u ^ (r & 7)) << 4));
}

// ---------------------------------------------------------------------------
// Preprocess kernels
// ---------------------------------------------------------------------------
__global__ void convert_x_kernel(const float* __restrict__ x) {
    size_t i = ((size_t)blockIdx.x * 256 + threadIdx.x) * 4;
    float4 v = *(const float4*)(x + i);
    *(uint2*)&g_x[i] = make_uint2(cvt2h(v.x, v.y), cvt2h(v.z, v.w));
}

__global__ void repack_wqkv_kernel(const float* __restrict__ Wq,
                                   const float* __restrict__ Wk,
                                   const float* __restrict__ Wv,
                                   const float* __restrict__ bq,
                                   const float* __restrict__ bk,
                                   const float* __restrict__ bv) {
    __shared__ float t[64][65];
    const int tid = threadIdx.x;
    const int k0 = blockIdx.x * 64;
    const int cy = blockIdx.y;            // 0..47
    const int proj = cy >> 4, h = cy & 15;
    const float* W = (proj == 0) ? Wq : (proj == 1 ? Wk : Wv);
    const float* base = W + (size_t)h * DMODEL * DHEAD;
    if (k0 == 0 && tid < 64) {
        const float* bb = (proj == 0) ? bq : (proj == 1 ? bk : bv);
        g_bqkv[proj*1024 + h*64 + tid] = bb[h*64 + tid];
    }
    #pragma unroll
    for (int it = 0; it < 4; ++it) {
        int idx = it*256 + tid;
        int r = idx >> 4;
        int c4 = (idx & 15) << 2;
        float4 v = *(const float4*)(base + (size_t)(k0 + r)*DHEAD + c4);
        t[r][c4+0] = v.x; t[r][c4+1] = v.y; t[r][c4+2] = v.z; t[r][c4+3] = v.w;
    }
    __syncthreads();
    const int n0 = proj*1024 + h*64;
    #pragma unroll
    for (int it = 0; it < 4; ++it) {
        int idx = it*256 + tid;
        int e = idx >> 4;
        int kk = (idx & 15) << 2;
        size_t off = (size_t)(n0 + e)*DMODEL + k0 + kk;
        *(uint2*)&g_wqkv[off] = make_uint2(cvt2h(t[kk+0][e], t[kk+1][e]),
                                           cvt2h(t[kk+2][e], t[kk+3][e]));
    }
}

__global__ void repack_wo_kernel(const float* __restrict__ Wo) {
    __shared__ float t[64][65];
    const int tid = threadIdx.x;
    const int k0 = blockIdx.x * 64;
    const int n0 = blockIdx.y * 64;
    #pragma unroll
    for (int it = 0; it < 4; ++it) {
        int idx = it*256 + tid;
        int r = idx >> 4;
        int c4 = (idx & 15) << 2;
        float4 v = *(const float4*)(Wo + (size_t)(k0 + r)*DMODEL + n0 + c4);
        t[r][c4+0] = v.x; t[r][c4+1] = v.y; t[r][c4+2] = v.z; t[r][c4+3] = v.w;
    }
    __syncthreads();
    #pragma unroll
    for (int it = 0; it < 4; ++it) {
        int idx = it*256 + tid;
        int e = idx >> 4;
        int kk = (idx & 15) << 2;
        size_t off = (size_t)(n0 + e)*DMODEL + k0 + kk;
        *(uint2*)&g_wo[off] = make_uint2(cvt2h(t[kk+0][e], t[kk+1][e]),
                                         cvt2h(t[kk+2][e], t[kk+3][e]));
    }
}

// ---------------------------------------------------------------------------
// mma.sync fp16 GEMM (R10 configuration — best measured).
// 256 threads, 8 warps (2m x 4n), warp tile 64x32, K-chunk 64,
// 3-stage cp.async ring, one sync per chunk. Stage = A|B = 32KB.
// MODE 0: A=g_x, B=g_wqkv, bias=g_bqkv -> g_q (scaled log2e/8), g_k, g_v
// MODE 1: A=g_z, B=g_wo, bias=bo -> Cout fp32
// ---------------------------------------------------------------------------
#define BKC 64
#define GSTAGE 32768u
#define GEMM_SMEM (3*32768)
#define GKT (DMODEL/BKC)   /* 16 chunks */

template<int MODE>
__global__ __launch_bounds__(256)
void mma_gemm_kernel(const float* __restrict__ bias_ext, float* __restrict__ Cout) {
    extern __shared__ char smem[];
    const uint32_t sbase = smem_u32(smem);
    const int tid  = threadIdx.x;
    const int lane = tid & 31;
    const int wid  = tid >> 5;
    const int wm   = wid & 1;
    const int wn   = wid >> 1;
    const int m0 = blockIdx.y * 128;
    const int n0 = blockIdx.x * 128;

    const __half* A = (MODE == 0) ? g_x : g_z;
    const __half* B = (MODE == 0) ? g_wqkv : g_wo;

    // cp.async descriptors: 8 x 16B per thread per stage
    const __half* gsrc[8];
    uint32_t soff[8];
    #pragma unroll
    for (int c = 0; c < 8; ++c) {
        int linear = c*256 + tid;          // 0..2047
        int tile = linear >> 10;           // 0:A 1:B
        int idx  = linear & 1023;
        int r = idx >> 3, u = idx & 7;
        const __half* bp = tile ? B : A;
        int rowbase = tile ? n0 : m0;
        gsrc[c] = bp + (size_t)(rowbase + r)*DMODEL + u*8;
        soff[c] = (uint32_t)tile*16384u + swz128(r, u);
    }

    const int a_r  = lane & 15;
    const int lu   = lane >> 4;
    const int b_r  = (lane & 7) + ((lane >> 3) & 1) * 8;

    float acc[4][4][4] = {};

    // prologue: stages 0, 1
    #pragma unroll
    for (int s = 0; s < 2; ++s) {
        #pragma unroll
        for (int c = 0; c < 8; ++c)
            cpasync16(sbase + s*GSTAGE + soff[c], gsrc[c] + s*BKC);
        asm volatile("cp.async.commit_group;" ::: "memory");
    }

    #pragma unroll 1
    for (int kt = 0; kt < GKT; ++kt) {
        if (kt < GKT - 1) asm volatile("cp.async.wait_group 1;" ::: "memory");
        else              asm volatile("cp.async.wait_group 0;" ::: "memory");
        __syncthreads();
        if (kt + 2 < GKT) {
            uint32_t st = sbase + (uint32_t)((kt + 2) % 3) * GSTAGE;
            #pragma unroll
            for (int c = 0; c < 8; ++c)
                cpasync16(st + soff[c], gsrc[c] + (kt + 2)*BKC);
            asm volatile("cp.async.commit_group;" ::: "memory");
        }

        const uint32_t st = sbase + (uint32_t)(kt % 3) * GSTAGE;
        #pragma unroll
        for (int ks = 0; ks < 4; ++ks) {
            const int u = ks*2 + lu;
            uint32_t ah[4][4];
            #pragma unroll
            for (int mi = 0; mi < 4; ++mi) {
                uint32_t so = swz128(wm*64 + mi*16 + a_r, u);
                ldsm4(ah[mi][0], ah[mi][1], ah[mi][2], ah[mi][3], st + so);
            }
            uint32_t bh[4][2];
            #pragma unroll
            for (int g = 0; g < 2; ++g) {
                uint32_t so = swz128(wn*32 + g*16 + b_r, u);
                uint32_t t0, t1, t2, t3;
                ldsm4(t0, t1, t2, t3, st + 16384u + so);
                bh[g*2][0] = t0; bh[g*2][1] = t2;
                bh[g*2+1][0] = t1; bh[g*2+1][1] = t3;
            }
            #pragma unroll
            for (int mi = 0; mi < 4; ++mi)
                #pragma unroll
                for (int nb = 0; nb < 4; ++nb)
                    mma16816(acc[mi][nb], ah[mi], bh[nb]);
        }
    }

    // epilogue
    const float* bias = (MODE == 0) ? g_bqkv : bias_ext;
    #pragma unroll
    for (int nb = 0; nb < 4; ++nb) {
        const int ncol = n0 + wn*32 + nb*8 + (lane & 3)*2;
        const float b0 = bias[ncol], b1 = bias[ncol + 1];
        #pragma unroll
        for (int mi = 0; mi < 4; ++mi) {
            const int m = m0 + wm*64 + mi*16 + (lane >> 2);
            float v00 = acc[mi][nb][0] + b0, v01 = acc[mi][nb][1] + b1; // row m
            float v10 = acc[mi][nb][2] + b0, v11 = acc[mi][nb][3] + b1; // row m+8
            if (MODE == 0) {
                const int proj = ncol >> 10, h = (ncol >> 6) & 15, e0 = ncol & 63;
                if (proj == 0) { v00 *= QSCALE; v01 *= QSCALE; v10 *= QSCALE; v11 *= QSCALE; }
                const int b = m >> 11, s = m & 2047;
                __half* dst = (proj == 0 ? g_q : (proj == 1 ? g_k : g_v))
                            + (((size_t)(b*NH + h))*SEQ + s)*DHEAD + e0;
                *(uint32_t*)dst = cvt2h(v00, v01);
                *(uint32_t*)(dst + 8*DHEAD) = cvt2h(v10, v11);
            } else {
                *(float2*)(Cout + (size_t)m*DMODEL + ncol)       = make_float2(v00, v01);
                *(float2*)(Cout + (size_t)(m + 8)*DMODEL + ncol) = make_float2(v10, v11);
            }
        }
    }
}

// ---------------------------------------------------------------------------
// Flash attention (R10 geometry) + fp16 softmax (ex2.f16x2) + ones-column
// row-sum MMA (l computed on tensor core; no FADDs, no shuffles).
// 256 threads, 8 warps x 16 q-rows; KV tiles of 64, 3-stage.
// SMEM: [0,16K) Q [128][64]; slot s at 16384+s*16384: K(8K)|V(8K).
// ---------------------------------------------------------------------------
#define ATTN_SMEM (16384 + 3*16384)
#define AKT (SEQ/BK)   /* 32 tiles */

__global__ __launch_bounds__(256)
void attn_mma_kernel() {
    extern __shared__ char smem[];
    const uint32_t sb = smem_u32(smem);
    const int tid  = threadIdx.x;
    const int lane = tid & 31;
    const int w    = tid >> 5;
    const int bh   = blockIdx.y;
    const int s0   = blockIdx.x * BQ;

    const __half* q_g = g_q + ((size_t)bh*SEQ + s0)*DHEAD;
    const __half* k_g = g_k + (size_t)bh*SEQ*DHEAD;
    const __half* v_g = g_v + (size_t)bh*SEQ*DHEAD;

    const __half* t_src[4];
    uint32_t t_soff[4];
    #pragma unroll
    for (int c = 0; c < 4; ++c) {
        int linear = c*256 + tid;
        int tile = linear >> 9;            // 0:K 1:V
        int idx  = linear & 511;
        int r = idx >> 3, u = idx & 7;
        t_src[c] = (tile ? v_g : k_g) + (size_t)r*DHEAD + u*8;
        t_soff[c] = (uint32_t)tile*8192u + swz128(r, u);
    }

    #pragma unroll
    for (int c = 0; c < 4; ++c) {
        int idx = c*256 + tid;
        int r = idx >> 3, u = idx & 7;
        cpasync16(sb + swz128(r, u), q_g + (size_t)r*DHEAD + u*8);
    }
    #pragma unroll
    for (int c = 0; c < 4; ++c) cpasync16(sb + 16384u + t_soff[c], t_src[c]);
    asm volatile("cp.async.commit_group;" ::: "memory");
    #pragma unroll
    for (int c = 0; c < 4; ++c) cpasync16(sb + 32768u + t_soff[c], t_src[c] + (size_t)BK*DHEAD);
    asm volatile("cp.async.commit_group;" ::: "memory");

    const int a_r = lane & 15;
    const int lu  = lane >> 4;
    const int b_r = (lane & 7) + ((lane >> 3) & 1) * 8;

    asm volatile("cp.async.wait_group 1;" ::: "memory");
    __syncthreads();
    uint32_t qh[4][4];
    #pragma unroll
    for (int ks = 0; ks < 4; ++ks) {
        uint32_t so = swz128(w*16 + a_r, ks*2 + lu);
        ldsm4(qh[ks][0], qh[ks][1], qh[ks][2], qh[ks][3], sb + so);
    }

    float oacc[8][4] = {};
    float lacc[4] = {};                        // ones-column row sums
    const uint32_t bones[2] = {0x3C003C00u, 0x3C003C00u};   // fp16 1.0 x4

    #pragma unroll 1
    for (int kt = 0; kt < AKT; ++kt) {
        if (kt < AKT - 1) asm volatile("cp.async.wait_group 1;" ::: "memory");
        else              asm volatile("cp.async.wait_group 0;" ::: "memory");
        __syncthreads();
        if (kt + 2 < AKT) {
            uint32_t st = sb + 16384u + (uint32_t)((kt + 2) % 3) * 16384u;
            #pragma unroll
            for (int c = 0; c < 4; ++c)
                cpasync16(st + t_soff[c], t_src[c] + (size_t)(kt + 2)*BK*DHEAD);
            asm volatile("cp.async.commit_group;" ::: "memory");
        }
        const uint32_t st = sb + 16384u + (uint32_t)(kt % 3) * 16384u;

        // ---- QK: S' = q' k^T (q' pre-scaled by log2e/8) ----
        float sacc[8][4] = {};
        #pragma unroll
        for (int ks = 0; ks < 4; ++ks) {
            uint32_t kh2[8][2];
            #pragma unroll
            for (int g = 0; g < 4; ++g) {
                uint32_t so = swz128(g*16 + b_r, ks*2 + lu);
                uint32_t t0, t1, t2, t3;
                ldsm4(t0, t1, t2, t3, st + so);
                kh2[g*2][0] = t0; kh2[g*2][1] = t2;
                kh2[g*2+1][0] = t1; kh2[g*2+1][1] = t3;
            }
            #pragma unroll
            for (int nb = 0; nb < 8; ++nb)
                mma16816(sacc[nb], qh[ks], kh2[nb]);
        }

        // ---- p = 2^s in fp16 (pack then ex2.f16x2) ----
        uint32_t ph[4][4];
        #pragma unroll
        for (int nb = 0; nb < 8; ++nb) {
            const int ks = nb >> 1;
            const int rb = (nb & 1) * 2;
            ph[ks][rb+0] = ex2h2(cvt2h(sacc[nb][0], sacc[nb][1]));
            ph[ks][rb+1] = ex2h2(cvt2h(sacc[nb][2], sacc[nb][3]));
        }

        // ---- PV: O += P V ; l += P * ones ----
        #pragma unroll
        for (int ks = 0; ks < 4; ++ks) {
            uint32_t vh2[8][2];
            #pragma unroll
            for (int np = 0; np < 4; ++np) {
                uint32_t so = swz128(ks*16 + b_r, np*2 + lu);
                uint32_t t0, t1, t2, t3;
                ldsm4t(t0, t1, t2, t3, st + 8192u + so);
                vh2[np*2][0] = t0; vh2[np*2][1] = t1;
                vh2[np*2+1][0] = t2; vh2[np*2+1][1] = t3;
            }
            #pragma unroll
            for (int nb = 0; nb < 8; ++nb)
                mma16816(oacc[nb], ph[ks], vh2[nb]);
            mma16816(lacc, ph[ks], bones);
        }
    }

    // l(row) is replicated across all lanes' d[0] (row r) and d[2] (row r+8)
    const float inv0 = 1.0f / lacc[0], inv1 = 1.0f / lacc[2];
    const int b = bh >> 4, h = bh & 15;
    const int r0 = s0 + w*16 + (lane >> 2);
    #pragma unroll
    for (int nb = 0; nb < 8; ++nb) {
        const int c = h*64 + nb*8 + (lane & 3)*2;
        size_t o0 = ((size_t)b*SEQ + r0)*DMODEL + c;
        *(uint32_t*)&g_z[o0] =
            cvt2h(oacc[nb][0]*inv0, oacc[nb][1]*inv0);
        *(uint32_t*)&g_z[o0 + 8*DMODEL] =
            cvt2h(oacc[nb][2]*inv1, oacc[nb][3]*inv1);
    }
}

// ---------------------------------------------------------------------------
extern "C" void kernel_launch(void* const* d_in, const int* in_sizes, int n_in,
                              void* d_out, int out_size) {
    const float* x  = (const float*)d_in[0];
    const float* Wq = (const float*)d_in[1];
    const float* bq = (const float*)d_in[2];
    const float* Wk = (const float*)d_in[3];
    const float* bk = (const float*)d_in[4];
    const float* Wv = (const float*)d_in[5];
    const float* bv = (const float*)d_in[6];
    const float* Wo = (const float*)d_in[7];
    const float* bo = (const float*)d_in[8];
    float* out = (float*)d_out;

    cudaFuncSetAttribute(attn_mma_kernel,
                         cudaFuncAttributeMaxDynamicSharedMemorySize, ATTN_SMEM);
    cudaFuncSetAttribute(mma_gemm_kernel<0>,
                         cudaFuncAttributeMaxDynamicSharedMemorySize, GEMM_SMEM);
    cudaFuncSetAttribute(mma_gemm_kernel<1>,
                         cudaFuncAttributeMaxDynamicSharedMemorySize, GEMM_SMEM);

    // preprocessing
    convert_x_kernel<<<(MTOT*DMODEL)/1024, 256>>>(x);
    repack_wqkv_kernel<<<dim3(16, 48), 256>>>(Wq, Wk, Wv, bq, bk, bv);
    repack_wo_kernel<<<dim3(16, 16), 256>>>(Wo);

    // QKV projection (fp16) -> g_q (scaled log2e/8), g_k, g_v
    mma_gemm_kernel<0><<<dim3(24, 64), 256, GEMM_SMEM>>>(nullptr, nullptr);

    // flash attention (fp16 tensor core, fp16 softmax, ones-column l) -> g_z
    attn_mma_kernel<<<dim3(SEQ/BQ, BATCH*NH), 256, ATTN_SMEM>>>();

    // output projection (fp16) -> out
    mma_gemm_kernel<1><<<dim3(8, 64), 256, GEMM_SMEM>>>(bo, out);
}

// round 14
// speedup vs baseline: 1.1041x; 1.0164x over previous
#include <cuda_runtime.h>
#include <cuda_fp16.h>
#include <cstdint>
#include <math.h>

#define BATCH 4
#define SEQ 2048
#define DMODEL 1024
#define NH 16
#define DHEAD 64
#define MTOT (BATCH*SEQ)                 /* 8192 rows */
#define PSZ (BATCH*NH*SEQ*DHEAD)         /* 8,388,608 */
#define BQ 128
#define BK 64
#define QSCALE 0.18033688011112042f     /* log2(e)/8 */

// ---------------- device scratch ----------------
__device__ __align__(128) __half  g_q[PSZ];                  // fp16, pre-scaled by log2e/8
__device__ __align__(128) __half  g_k[PSZ];
__device__ __align__(128) __half  g_v[PSZ];
__device__ __align__(128) __half  g_x[MTOT*DMODEL];
__device__ __align__(128) __half  g_z[MTOT*DMODEL];
__device__ __align__(128) __half  g_wqkv[3*DMODEL*DMODEL];   // [n=(proj,h,e)][k]
__device__ __align__(128) __half  g_wo[DMODEL*DMODEL];       // [n][k] = Wo^T
__device__ __align__(128) float   g_bqkv[3*DMODEL];

// ---------------- helpers ----------------
__device__ __forceinline__ uint32_t smem_u32(const void* p) {
    uint32_t a;
    asm("{ .reg .u64 t; cvta.to.shared.u64 t, %1; cvt.u32.u64 %0, t; }"
        : "=r"(a) : "l"(p));
    return a;
}
// pack two floats into fp16x2 (lo in low half, hi in high half)
__device__ __forceinline__ uint32_t cvt2h(float lo, float hi) {
    uint32_t r;
    asm("cvt.rn.f16x2.f32 %0, %1, %2;" : "=r"(r) : "f"(hi), "f"(lo));
    return r;
}
__device__ __forceinline__ uint32_t ex2h2(uint32_t s) {
    uint32_t r;
    asm("ex2.approx.f16x2 %0, %1;" : "=r"(r) : "r"(s));
    return r;
}
__device__ __forceinline__ void cpasync16(uint32_t saddr, const void* g) {
    asm volatile("cp.async.cg.shared.global [%0], [%1], 16;"
                 :: "r"(saddr), "l"(g) : "memory");
}
__device__ __forceinline__ void ldsm4(uint32_t& r0, uint32_t& r1,
                                      uint32_t& r2, uint32_t& r3, uint32_t addr) {
    asm volatile("ldmatrix.sync.aligned.m8n8.x4.shared.b16 {%0,%1,%2,%3}, [%4];"
                 : "=r"(r0), "=r"(r1), "=r"(r2), "=r"(r3) : "r"(addr));
}
__device__ __forceinline__ void ldsm4t(uint32_t& r0, uint32_t& r1,
                                       uint32_t& r2, uint32_t& r3, uint32_t addr) {
    asm volatile("ldmatrix.sync.aligned.m8n8.x4.trans.shared.b16 {%0,%1,%2,%3}, [%4];"
                 : "=r"(r0), "=r"(r1), "=r"(r2), "=r"(r3) : "r"(addr));
}
__device__ __forceinline__ void mma16816(float* d, const uint32_t* a, const uint32_t* b) {
    asm volatile("mma.sync.aligned.m16n8k16.row.col.f32.f16.f16.f32 "
                 "{%0,%1,%2,%3},{%4,%5,%6,%7},{%8,%9},{%0,%1,%2,%3};"
                 : "+f"(d[0]), "+f"(d[1]), "+f"(d[2]), "+f"(d[3])
                 : "r"(a[0]), "r"(a[1]), "r"(a[2]), "r"(a[3]),
                   "r"(b[0]), "r"(b[1]));
}
// fp16-accumulate variant: d = 2 x b32 regs (4 halves)
__device__ __forceinline__ void mma16816h(uint32_t* d, const uint32_t* a, const uint32_t* b) {
    asm volatile("mma.sync.aligned.m16n8k16.row.col.f16.f16.f16.f16 "
                 "{%0,%1},{%2,%3,%4,%5},{%6,%7},{%0,%1};"
                 : "+r"(d[0]), "+r"(d[1])
                 : "r"(a[0]), "r"(a[1]), "r"(a[2]), "r"(a[3]),
                   "r"(b[0]), "r"(b[1]));
}
// swizzle for [rows x 128B] tiles (8 x 16B units)
__device__ __forceinline__ uint32_t swz128(int r, int u) {
    return (uint32_t)(r * 128 + ((u ^ (r & 7)) << 4));
}

// ---------------------------------------------------------------------------
// Preprocess kernels
// ---------------------------------------------------------------------------
__global__ void convert_x_kernel(const float* __restrict__ x) {
    size_t i = ((size_t)blockIdx.x * 256 + threadIdx.x) * 4;
    float4 v = *(const float4*)(x + i);
    *(uint2*)&g_x[i] = make_uint2(cvt2h(v.x, v.y), cvt2h(v.z, v.w));
}

__global__ void repack_wqkv_kernel(const float* __restrict__ Wq,
                                   const float* __restrict__ Wk,
                                   const float* __restrict__ Wv,
                                   const float* __restrict__ bq,
                                   const float* __restrict__ bk,
                                   const float* __restrict__ bv) {
    __shared__ float t[64][65];
    const int tid = threadIdx.x;
    const int k0 = blockIdx.x * 64;
    const int cy = blockIdx.y;            // 0..47
    const int proj = cy >> 4, h = cy & 15;
    const float* W = (proj == 0) ? Wq : (proj == 1 ? Wk : Wv);
    const float* base = W + (size_t)h * DMODEL * DHEAD;
    if (k0 == 0 && tid < 64) {
        const float* bb = (proj == 0) ? bq : (proj == 1 ? bk : bv);
        g_bqkv[proj*1024 + h*64 + tid] = bb[h*64 + tid];
    }
    #pragma unroll
    for (int it = 0; it < 4; ++it) {
        int idx = it*256 + tid;
        int r = idx >> 4;
        int c4 = (idx & 15) << 2;
        float4 v = *(const float4*)(base + (size_t)(k0 + r)*DHEAD + c4);
        t[r][c4+0] = v.x; t[r][c4+1] = v.y; t[r][c4+2] = v.z; t[r][c4+3] = v.w;
    }
    __syncthreads();
    const int n0 = proj*1024 + h*64;
    #pragma unroll
    for (int it = 0; it < 4; ++it) {
        int idx = it*256 + tid;
        int e = idx >> 4;
        int kk = (idx & 15) << 2;
        size_t off = (size_t)(n0 + e)*DMODEL + k0 + kk;
        *(uint2*)&g_wqkv[off] = make_uint2(cvt2h(t[kk+0][e], t[kk+1][e]),
                                           cvt2h(t[kk+2][e], t[kk+3][e]));
    }
}

__global__ void repack_wo_kernel(const float* __restrict__ Wo) {
    __shared__ float t[64][65];
    const int tid = threadIdx.x;
    const int k0 = blockIdx.x * 64;
    const int n0 = blockIdx.y * 64;
    #pragma unroll
    for (int it = 0; it < 4; ++it) {
        int idx = it*256 + tid;
        int r = idx >> 4;
        int c4 = (idx & 15) << 2;
        float4 v = *(const float4*)(Wo + (size_t)(k0 + r)*DMODEL + n0 + c4);
        t[r][c4+0] = v.x; t[r][c4+1] = v.y; t[r][c4+2] = v.z; t[r][c4+3] = v.w;
    }
    __syncthreads();
    #pragma unroll
    for (int it = 0; it < 4; ++it) {
        int idx = it*256 + tid;
        int e = idx >> 4;
        int kk = (idx & 15) << 2;
        size_t off = (size_t)(n0 + e)*DMODEL + k0 + kk;
        *(uint2*)&g_wo[off] = make_uint2(cvt2h(t[kk+0][e], t[kk+1][e]),
                                         cvt2h(t[kk+2][e], t[kk+3][e]));
    }
}

// ---------------------------------------------------------------------------
// mma.sync fp16 GEMM (R10 configuration — best measured, unchanged).
// 256 threads, 8 warps (2m x 4n), warp tile 64x32, K-chunk 64,
// 3-stage cp.async ring, one sync per chunk. Stage = A|B = 32KB.
// ---------------------------------------------------------------------------
#define BKC 64
#define GSTAGE 32768u
#define GEMM_SMEM (3*32768)
#define GKT (DMODEL/BKC)   /* 16 chunks */

template<int MODE>
__global__ __launch_bounds__(256)
void mma_gemm_kernel(const float* __restrict__ bias_ext, float* __restrict__ Cout) {
    extern __shared__ char smem[];
    const uint32_t sbase = smem_u32(smem);
    const int tid  = threadIdx.x;
    const int lane = tid & 31;
    const int wid  = tid >> 5;
    const int wm   = wid & 1;
    const int wn   = wid >> 1;
    const int m0 = blockIdx.y * 128;
    const int n0 = blockIdx.x * 128;

    const __half* A = (MODE == 0) ? g_x : g_z;
    const __half* B = (MODE == 0) ? g_wqkv : g_wo;

    const __half* gsrc[8];
    uint32_t soff[8];
    #pragma unroll
    for (int c = 0; c < 8; ++c) {
        int linear = c*256 + tid;          // 0..2047
        int tile = linear >> 10;           // 0:A 1:B
        int idx  = linear & 1023;
        int r = idx >> 3, u = idx & 7;
        const __half* bp = tile ? B : A;
        int rowbase = tile ? n0 : m0;
        gsrc[c] = bp + (size_t)(rowbase + r)*DMODEL + u*8;
        soff[c] = (uint32_t)tile*16384u + swz128(r, u);
    }

    const int a_r  = lane & 15;
    const int lu   = lane >> 4;
    const int b_r  = (lane & 7) + ((lane >> 3) & 1) * 8;

    float acc[4][4][4] = {};

    #pragma unroll
    for (int s = 0; s < 2; ++s) {
        #pragma unroll
        for (int c = 0; c < 8; ++c)
            cpasync16(sbase + s*GSTAGE + soff[c], gsrc[c] + s*BKC);
        asm volatile("cp.async.commit_group;" ::: "memory");
    }

    #pragma unroll 1
    for (int kt = 0; kt < GKT; ++kt) {
        if (kt < GKT - 1) asm volatile("cp.async.wait_group 1;" ::: "memory");
        else              asm volatile("cp.async.wait_group 0;" ::: "memory");
        __syncthreads();
        if (kt + 2 < GKT) {
            uint32_t st = sbase + (uint32_t)((kt + 2) % 3) * GSTAGE;
            #pragma unroll
            for (int c = 0; c < 8; ++c)
                cpasync16(st + soff[c], gsrc[c] + (kt + 2)*BKC);
            asm volatile("cp.async.commit_group;" ::: "memory");
        }

        const uint32_t st = sbase + (uint32_t)(kt % 3) * GSTAGE;
        #pragma unroll
        for (int ks = 0; ks < 4; ++ks) {
            const int u = ks*2 + lu;
            uint32_t ah[4][4];
            #pragma unroll
            for (int mi = 0; mi < 4; ++mi) {
                uint32_t so = swz128(wm*64 + mi*16 + a_r, u);
                ldsm4(ah[mi][0], ah[mi][1], ah[mi][2], ah[mi][3], st + so);
            }
            uint32_t bh[4][2];
            #pragma unroll
            for (int g = 0; g < 2; ++g) {
                uint32_t so = swz128(wn*32 + g*16 + b_r, u);
                uint32_t t0, t1, t2, t3;
                ldsm4(t0, t1, t2, t3, st + 16384u + so);
                bh[g*2][0] = t0; bh[g*2][1] = t2;
                bh[g*2+1][0] = t1; bh[g*2+1][1] = t3;
            }
            #pragma unroll
            for (int mi = 0; mi < 4; ++mi)
                #pragma unroll
                for (int nb = 0; nb < 4; ++nb)
                    mma16816(acc[mi][nb], ah[mi], bh[nb]);
        }
    }

    // epilogue
    const float* bias = (MODE == 0) ? g_bqkv : bias_ext;
    #pragma unroll
    for (int nb = 0; nb < 4; ++nb) {
        const int ncol = n0 + wn*32 + nb*8 + (lane & 3)*2;
        const float b0 = bias[ncol], b1 = bias[ncol + 1];
        #pragma unroll
        for (int mi = 0; mi < 4; ++mi) {
            const int m = m0 + wm*64 + mi*16 + (lane >> 2);
            float v00 = acc[mi][nb][0] + b0, v01 = acc[mi][nb][1] + b1; // row m
            float v10 = acc[mi][nb][2] + b0, v11 = acc[mi][nb][3] + b1; // row m+8
            if (MODE == 0) {
                const int proj = ncol >> 10, h = (ncol >> 6) & 15, e0 = ncol & 63;
                if (proj == 0) { v00 *= QSCALE; v01 *= QSCALE; v10 *= QSCALE; v11 *= QSCALE; }
                const int b = m >> 11, s = m & 2047;
                __half* dst = (proj == 0 ? g_q : (proj == 1 ? g_k : g_v))
                            + (((size_t)(b*NH + h))*SEQ + s)*DHEAD + e0;
                *(uint32_t*)dst = cvt2h(v00, v01);
                *(uint32_t*)(dst + 8*DHEAD) = cvt2h(v10, v11);
            } else {
                *(float2*)(Cout + (size_t)m*DMODEL + ncol)       = make_float2(v00, v01);
                *(float2*)(Cout + (size_t)(m + 8)*DMODEL + ncol) = make_float2(v10, v11);
            }
        }
    }
}

// ---------------------------------------------------------------------------
// Flash attention: QK with fp16 ACCUMULATE (mma f16.f16.f16.f16 — tests the
// half-rate-HMMA hypothesis; d regs are already packed half2 score pairs, so
// ex2.approx.f16x2 applies directly). PV + ones-column l stay fp32-accum.
// 256 threads, 8 warps x 16 q-rows; KV tiles of 64, 3-stage.
// SMEM: [0,16K) Q [128][64]; slot s at 16384+s*16384: K(8K)|V(8K).
// ---------------------------------------------------------------------------
#define ATTN_SMEM (16384 + 3*16384)
#define AKT (SEQ/BK)   /* 32 tiles */

__global__ __launch_bounds__(256)
void attn_mma_kernel() {
    extern __shared__ char smem[];
    const uint32_t sb = smem_u32(smem);
    const int tid  = threadIdx.x;
    const int lane = tid & 31;
    const int w    = tid >> 5;
    const int bh   = blockIdx.y;
    const int s0   = blockIdx.x * BQ;

    const __half* q_g = g_q + ((size_t)bh*SEQ + s0)*DHEAD;
    const __half* k_g = g_k + (size_t)bh*SEQ*DHEAD;
    const __half* v_g = g_v + (size_t)bh*SEQ*DHEAD;

    const __half* t_src[4];
    uint32_t t_soff[4];
    #pragma unroll
    for (int c = 0; c < 4; ++c) {
        int linear = c*256 + tid;
        int tile = linear >> 9;            // 0:K 1:V
        int idx  = linear & 511;
        int r = idx >> 3, u = idx & 7;
        t_src[c] = (tile ? v_g : k_g) + (size_t)r*DHEAD + u*8;
        t_soff[c] = (uint32_t)tile*8192u + swz128(r, u);
    }

    #pragma unroll
    for (int c = 0; c < 4; ++c) {
        int idx = c*256 + tid;
        int r = idx >> 3, u = idx & 7;
        cpasync16(sb + swz128(r, u), q_g + (size_t)r*DHEAD + u*8);
    }
    #pragma unroll
    for (int c = 0; c < 4; ++c) cpasync16(sb + 16384u + t_soff[c], t_src[c]);
    asm volatile("cp.async.commit_group;" ::: "memory");
    #pragma unroll
    for (int c = 0; c < 4; ++c) cpasync16(sb + 32768u + t_soff[c], t_src[c] + (size_t)BK*DHEAD);
    asm volatile("cp.async.commit_group;" ::: "memory");

    const int a_r = lane & 15;
    const int lu  = lane >> 4;
    const int b_r = (lane & 7) + ((lane >> 3) & 1) * 8;

    asm volatile("cp.async.wait_group 1;" ::: "memory");
    __syncthreads();
    uint32_t qh[4][4];
    #pragma unroll
    for (int ks = 0; ks < 4; ++ks) {
        uint32_t so = swz128(w*16 + a_r, ks*2 + lu);
        ldsm4(qh[ks][0], qh[ks][1], qh[ks][2], qh[ks][3], sb + so);
    }

    float oacc[8][4] = {};
    float lacc[4] = {};                        // ones-column row sums (fp32)
    const uint32_t bones[2] = {0x3C003C00u, 0x3C003C00u};   // fp16 1.0 x4

    #pragma unroll 1
    for (int kt = 0; kt < AKT; ++kt) {
        if (kt < AKT - 1) asm volatile("cp.async.wait_group 1;" ::: "memory");
        else              asm volatile("cp.async.wait_group 0;" ::: "memory");
        __syncthreads();
        if (kt + 2 < AKT) {
            uint32_t st = sb + 16384u + (uint32_t)((kt + 2) % 3) * 16384u;
            #pragma unroll
            for (int c = 0; c < 4; ++c)
                cpasync16(st + t_soff[c], t_src[c] + (size_t)(kt + 2)*BK*DHEAD);
            asm volatile("cp.async.commit_group;" ::: "memory");
        }
        const uint32_t st = sb + 16384u + (uint32_t)(kt % 3) * 16384u;

        // ---- QK: S' = q' k^T, fp16 accumulate ----
        uint32_t sacch[8][2] = {};   // zero-init == fp16 zeros
        #pragma unroll
        for (int ks = 0; ks < 4; ++ks) {
            uint32_t kh2[8][2];
            #pragma unroll
            for (int g = 0; g < 4; ++g) {
                uint32_t so = swz128(g*16 + b_r, ks*2 + lu);
                uint32_t t0, t1, t2, t3;
                ldsm4(t0, t1, t2, t3, st + so);
                kh2[g*2][0] = t0; kh2[g*2][1] = t2;
                kh2[g*2+1][0] = t1; kh2[g*2+1][1] = t3;
            }
            #pragma unroll
            for (int nb = 0; nb < 8; ++nb)
                mma16816h(sacch[nb], qh[ks], kh2[nb]);
        }

        // ---- p = 2^s directly on fp16 pairs ----
        uint32_t ph[4][4];
        #pragma unroll
        for (int nb = 0; nb < 8; ++nb) {
            const int ks = nb >> 1;
            const int rb = (nb & 1) * 2;
            ph[ks][rb+0] = ex2h2(sacch[nb][0]);
            ph[ks][rb+1] = ex2h2(sacch[nb][1]);
        }

        // ---- PV: O += P V ; l += P * ones (fp32 accum) ----
        #pragma unroll
        for (int ks = 0; ks < 4; ++ks) {
            uint32_t vh2[8][2];
            #pragma unroll
            for (int np = 0; np < 4; ++np) {
                uint32_t so = swz128(ks*16 + b_r, np*2 + lu);
                uint32_t t0, t1, t2, t3;
                ldsm4t(t0, t1, t2, t3, st + 8192u + so);
                vh2[np*2][0] = t0; vh2[np*2][1] = t1;
                vh2[np*2+1][0] = t2; vh2[np*2+1][1] = t3;
            }
            #pragma unroll
            for (int nb = 0; nb < 8; ++nb)
                mma16816(oacc[nb], ph[ks], vh2[nb]);
            mma16816(lacc, ph[ks], bones);
        }
    }

    // l(row) replicated across lanes' d[0] (row r) and d[2] (row r+8)
    const float inv0 = 1.0f / lacc[0], inv1 = 1.0f / lacc[2];
    const int b = bh >> 4, h = bh & 15;
    const int r0 = s0 + w*16 + (lane >> 2);
    #pragma unroll
    for (int nb = 0; nb < 8; ++nb) {
        const int c = h*64 + nb*8 + (lane & 3)*2;
        size_t o0 = ((size_t)b*SEQ + r0)*DMODEL + c;
        *(uint32_t*)&g_z[o0] =
            cvt2h(oacc[nb][0]*inv0, oacc[nb][1]*inv0);
        *(uint32_t*)&g_z[o0 + 8*DMODEL] =
            cvt2h(oacc[nb][2]*inv1, oacc[nb][3]*inv1);
    }
}

// ---------------------------------------------------------------------------
extern "C" void kernel_launch(void* const* d_in, const int* in_sizes, int n_in,
                              void* d_out, int out_size) {
    const float* x  = (const float*)d_in[0];
    const float* Wq = (const float*)d_in[1];
    const float* bq = (const float*)d_in[2];
    const float* Wk = (const float*)d_in[3];
    const float* bk = (const float*)d_in[4];
    const float* Wv = (const float*)d_in[5];
    const float* bv = (const float*)d_in[6];
    const float* Wo = (const float*)d_in[7];
    const float* bo = (const float*)d_in[8];
    float* out = (float*)d_out;

    cudaFuncSetAttribute(attn_mma_kernel,
                         cudaFuncAttributeMaxDynamicSharedMemorySize, ATTN_SMEM);
    cudaFuncSetAttribute(mma_gemm_kernel<0>,
                         cudaFuncAttributeMaxDynamicSharedMemorySize, GEMM_SMEM);
    cudaFuncSetAttribute(mma_gemm_kernel<1>,
                         cudaFuncAttributeMaxDynamicSharedMemorySize, GEMM_SMEM);

    // preprocessing
    convert_x_kernel<<<(MTOT*DMODEL)/1024, 256>>>(x);
    repack_wqkv_kernel<<<dim3(16, 48), 256>>>(Wq, Wk, Wv, bq, bk, bv);
    repack_wo_kernel<<<dim3(16, 16), 256>>>(Wo);

    // QKV projection (fp16) -> g_q (scaled log2e/8), g_k, g_v
    mma_gemm_kernel<0><<<dim3(24, 64), 256, GEMM_SMEM>>>(nullptr, nullptr);

    // flash attention (fp16-accum QK, fp16 softmax, ones-column l) -> g_z
    attn_mma_kernel<<<dim3(SEQ/BQ, BATCH*NH), 256, ATTN_SMEM>>>();

    // output projection (fp16) -> out
    mma_gemm_kernel<1><<<dim3(8, 64), 256, GEMM_SMEM>>>(bo, out);
}